// round 1
// baseline (speedup 1.0000x reference)
#include <cuda_runtime.h>
#include <math.h>

#define D        64
#define BM       128   // rows per block
#define CK       128   // codebook chunk
#define TPB      256
#define XS       132   // smem row stride (padded, 16B-aligned, conflict-free)

// smem: xst[64][XS] | cst[64][XS] | c2s[CK]
#define SMEM_FLOATS (2 * 64 * XS + CK)
#define SMEM_BYTES  (SMEM_FLOATS * 4)

__device__ double g_mse_sum;
__device__ int    g_counts[8192];

__global__ void vq_zero(int K) {
    int t = threadIdx.x;
    if (t == 0) g_mse_sum = 0.0;
    for (int k = t; k < K; k += blockDim.x) g_counts[k] = 0;
}

__global__ void __launch_bounds__(TPB, 2)
vq_main(const float* __restrict__ x, const float* __restrict__ cb,
        int N, int K, float* __restrict__ outQ, float* __restrict__ outT,
        int writeExtras)
{
    extern __shared__ float sm[];
    float* xst = sm;                 // [64][XS]  (d-major, row-minor)
    float* cst = sm + 64 * XS;       // [64][XS]  (d-major, code-minor)
    float* c2s = sm + 2 * 64 * XS;   // [CK]

    const int tid = threadIdx.x;
    const int tx = tid & 15;         // code group
    const int ty = tid >> 4;         // row group
    const int rowBase = blockIdx.x * BM;

    // ---- load x tile, transposed into smem ----
    for (int i = tid; i < BM * D; i += TPB) {
        int r = i >> 6, d = i & 63;
        int gr = rowBase + r; if (gr >= N) gr = N - 1;
        xst[d * XS + r] = x[(size_t)gr * D + d];
    }

    float runMin[8];
    int   runIdx[8];
#pragma unroll
    for (int i = 0; i < 8; i++) { runMin[i] = 3.4e38f; runIdx[i] = 0x7fffffff; }

    for (int kc = 0; kc < K; kc += CK) {
        __syncthreads();
        // load codebook chunk, transposed
        for (int i = tid; i < CK * D; i += TPB) {
            int k = i >> 6, d = i & 63;
            cst[d * XS + k] = cb[(size_t)(kc + k) * D + d];
        }
        __syncthreads();
        if (tid < CK) {
            float s = 0.f;
#pragma unroll
            for (int d = 0; d < D; d++) { float v = cst[d * XS + tid]; s = fmaf(v, v, s); }
            c2s[tid] = s;
        }
        __syncthreads();

        float acc[8][8];
#pragma unroll
        for (int i = 0; i < 8; i++)
#pragma unroll
            for (int j = 0; j < 8; j++) acc[i][j] = 0.f;

#pragma unroll 4
        for (int d = 0; d < D; d++) {
            float4 a0 = *(const float4*)&xst[d * XS + ty * 8];
            float4 a1 = *(const float4*)&xst[d * XS + ty * 8 + 4];
            float4 b0 = *(const float4*)&cst[d * XS + tx * 8];
            float4 b1 = *(const float4*)&cst[d * XS + tx * 8 + 4];
            float av[8] = {a0.x, a0.y, a0.z, a0.w, a1.x, a1.y, a1.z, a1.w};
            float bv[8] = {b0.x, b0.y, b0.z, b0.w, b1.x, b1.y, b1.z, b1.w};
#pragma unroll
            for (int i = 0; i < 8; i++)
#pragma unroll
                for (int j = 0; j < 8; j++)
                    acc[i][j] = fmaf(av[i], bv[j], acc[i][j]);
        }

        // fold into running argmin: dist = |c|^2 - 2 x.c  (|x|^2 drops out)
#pragma unroll
        for (int j = 0; j < 8; j++) {
            float c2 = c2s[tx * 8 + j];
            int kg = kc + tx * 8 + j;
#pragma unroll
            for (int i = 0; i < 8; i++) {
                float dist = fmaf(-2.f, acc[i][j], c2);
                if (dist < runMin[i]) { runMin[i] = dist; runIdx[i] = kg; }
            }
        }
    }

    __syncthreads();
    // ---- cross-thread argmin reduction (reuse cst region) ----
    float* redV  = cst;                         // [BM][16]
    int*   redI  = (int*)(cst + BM * 16);       // [BM][16]
    int*   bestI = (int*)(cst + BM * 32);       // [BM]
#pragma unroll
    for (int i = 0; i < 8; i++) {
        int r = ty * 8 + i;
        redV[r * 16 + tx] = runMin[i];
        redI[r * 16 + tx] = runIdx[i];
    }
    __syncthreads();
    if (tid < BM) {
        float bv = redV[tid * 16]; int bi = redI[tid * 16];
#pragma unroll
        for (int t = 1; t < 16; t++) {
            float v = redV[tid * 16 + t]; int ix = redI[tid * 16 + t];
            if (v < bv || (v == bv && ix < bi)) { bv = v; bi = ix; }
        }
        bestI[tid] = bi;
        int gr = rowBase + tid;
        if (gr < N) {
            if (writeExtras) outT[gr] = (float)bi;
            atomicAdd(&g_counts[bi], 1);
        }
    }
    __syncthreads();

    // ---- epilogue: quantized gather + MSE (one warp per row group) ----
    const int warp = tid >> 5, lane = tid & 31;
    float lsum = 0.f;
    for (int r = warp; r < BM; r += 8) {
        int gr = rowBase + r;
        if (gr >= N) continue;
        int bi = bestI[r];
        const float* crow = cb + (size_t)bi * D;
        float* qrow = outQ + (size_t)gr * D;
#pragma unroll
        for (int h = 0; h < 2; h++) {
            int d = h * 32 + lane;
            float cv = __ldg(&crow[d]);
            float xv = xst[d * XS + r];
            float diff = xv - cv;
            lsum = fmaf(diff, diff, lsum);
            qrow[d] = cv;
        }
    }
    // block reduce lsum -> one double atomicAdd
#pragma unroll
    for (int o = 16; o > 0; o >>= 1)
        lsum += __shfl_down_sync(0xffffffffu, lsum, o);
    __shared__ float wsum[8];
    if (lane == 0) wsum[warp] = lsum;
    __syncthreads();
    if (tid == 0) {
        float s = 0.f;
#pragma unroll
        for (int w = 0; w < 8; w++) s += wsum[w];
        atomicAdd(&g_mse_sum, (double)s);
    }
}

__global__ void vq_final(float* __restrict__ outS, int N, int K) {
    const int tid = threadIdx.x;
    float ent = 0.f;
    for (int k = tid; k < K; k += blockDim.x) {
        float p = (float)g_counts[k] / (float)N;
        ent += p * logf(p + 1e-10f);
    }
#pragma unroll
    for (int o = 16; o > 0; o >>= 1)
        ent += __shfl_down_sync(0xffffffffu, ent, o);
    __shared__ float ws[32];
    const int warp = tid >> 5, lane = tid & 31;
    if (lane == 0) ws[warp] = ent;
    __syncthreads();
    if (tid == 0) {
        float e = 0.f;
        int nw = (blockDim.x + 31) >> 5;
        for (int w = 0; w < nw; w++) e += ws[w];
        float mse = (float)(g_mse_sum / ((double)N * (double)D));
        outS[0] = 1.25f * mse;  // vq_loss
        outS[1] = 0.25f * mse;  // commitment_loss
        outS[2] = mse;          // codebook_loss
        outS[3] = expf(-e);     // perplexity
    }
}

extern "C" void kernel_launch(void* const* d_in, const int* in_sizes, int n_in,
                              void* d_out, int out_size)
{
    const float* x  = (const float*)d_in[0];
    const float* cb = (const float*)d_in[1];
    const int total = in_sizes[0];
    const int K = in_sizes[1] / D;
    const int N = total / D;

    float* out = (float*)d_out;
    const int writeExtras = (out_size >= total + N + 4) ? 1 : 0;
    float* outQ = out;
    float* outT = writeExtras ? out + total : out;          // dummy if absent
    float* outS = writeExtras ? out + total + N : nullptr;

    cudaFuncSetAttribute(vq_main, cudaFuncAttributeMaxDynamicSharedMemorySize, SMEM_BYTES);

    vq_zero<<<1, 1024>>>(K);
    const int grid = (N + BM - 1) / BM;
    vq_main<<<grid, TPB, SMEM_BYTES>>>(x, cb, N, K, outQ, outT, writeExtras);
    if (writeExtras)
        vq_final<<<1, 1024>>>(outS, N, K);
}

// round 5
// speedup vs baseline: 2.2861x; 2.2861x over previous
#include <cuda_runtime.h>
#include <cuda_fp16.h>
#include <math.h>
#include <stdint.h>

#define D        64
#define BM       128            // rows per CTA
#define KCODES   1024
#define CHUNK    128            // codes per chunk
#define NCHUNKS  (KCODES / CHUNK)
#define TPB      256
#define PAD      72             // halves per row (144B rows: 8-row ldmatrix phases conflict-free)

// SMEM byte offsets
#define OFF_C2     0            // 1024 f32
#define OFF_REDV   4096         // 128*2 f32
#define OFF_REDI   5120         // 128*2 i32
#define OFF_BESTI  6144         // 128 i32
#define OFF_WSUM   6656         // 8 f32
#define OFF_AHI    8192         // 128*72 half = 18432B
#define OFF_ALO    26624        // 18432B
#define OFF_B      45056        // [term2][128*72 half] = 36864B (single buffer)
#define SMEM_TOTAL 81920

#define BTERM_BYTES 18432

__device__ double g_mse_sum;
__device__ int    g_counts[1024];
__device__ float  g_c2[1024];
__device__ __align__(16) __half g_cbh[KCODES * PAD];
__device__ __align__(16) __half g_cbl[KCODES * PAD];

__device__ __forceinline__ uint32_t smem_u32(const void* p) {
    uint32_t a;
    asm("{ .reg .u64 t; cvta.to.shared.u64 t, %1; cvt.u32.u64 %0, t; }" : "=r"(a) : "l"(p));
    return a;
}
#define LDSM_X4(r0, r1, r2, r3, addr) \
    asm volatile("ldmatrix.sync.aligned.m8n8.x4.shared.b16 {%0,%1,%2,%3}, [%4];" \
        : "=r"(r0), "=r"(r1), "=r"(r2), "=r"(r3) : "r"(addr))
#define MMA16816(c, a, b0, b1) \
    asm volatile("mma.sync.aligned.m16n8k16.row.col.f32.f16.f16.f32 " \
        "{%0,%1,%2,%3}, {%4,%5,%6,%7}, {%8,%9}, {%0,%1,%2,%3};" \
        : "+f"((c)[0]), "+f"((c)[1]), "+f"((c)[2]), "+f"((c)[3]) \
        : "r"((a)[0]), "r"((a)[1]), "r"((a)[2]), "r"((a)[3]), "r"(b0), "r"(b1))

// ---------------- prep: fp16-split codebook into padded images, |c|^2, zero accum ----------------
__global__ void vq_prep(const float* __restrict__ cb) {
    int k = blockIdx.x;       // code
    int d = threadIdx.x;      // 0..63
    float v = cb[k * D + d];
    __half hi = __float2half_rn(v);
    __half lo = __float2half_rn(v - __half2float(hi));
    g_cbh[k * PAD + d] = hi;
    g_cbl[k * PAD + d] = lo;
    if (d < 8) {              // zero the pad region deterministically
        g_cbh[k * PAD + 64 + d] = __half(0.f);
        g_cbl[k * PAD + 64 + d] = __half(0.f);
    }
    float sq = v * v;
#pragma unroll
    for (int o = 16; o > 0; o >>= 1) sq += __shfl_down_sync(0xffffffffu, sq, o);
    __shared__ float s2[2];
    if ((d & 31) == 0) s2[d >> 5] = sq;
    __syncthreads();
    if (d == 0) g_c2[k] = s2[0] + s2[1];
    if (k == 0) {
        if (d == 0) g_mse_sum = 0.0;
        for (int i = d; i < 1024; i += 64) g_counts[i] = 0;
    }
}

// ---------------- main ----------------
__global__ void __launch_bounds__(TPB)
vq_main(const float* __restrict__ x, const float* __restrict__ cb,
        int N, float* __restrict__ outQ, float* __restrict__ outT, int writeExtras)
{
    extern __shared__ char smc[];
    const uint32_t sb = smem_u32(smc);
    float*  c2s   = (float*)(smc + OFF_C2);
    float*  redV  = (float*)(smc + OFF_REDV);
    int*    redI  = (int*)(smc + OFF_REDI);
    int*    bestI = (int*)(smc + OFF_BESTI);
    float*  wsum  = (float*)(smc + OFF_WSUM);
    __half* Ahi   = (__half*)(smc + OFF_AHI);
    __half* Alo   = (__half*)(smc + OFF_ALO);
    float4* Bv    = (float4*)(smc + OFF_B);

    const int tid = threadIdx.x;
    const int warp = tid >> 5, lane = tid & 31;
    const int mblk = (warp & 3) * 32;    // 4 m-blocks of 32 rows
    const int nb   = warp >> 2;          // 2 n-blocks of 64 codes
    const int nblk = nb * 64;
    const int rowBase = blockIdx.x * BM;

    // load x tile, fp16-split into padded smem
    for (int i = tid; i < BM * D; i += TPB) {
        int r = i >> 6, d = i & 63;
        int gr = rowBase + r; if (gr >= N) gr = N - 1;
        float v = x[(size_t)gr * D + d];
        __half hi = __float2half_rn(v);
        Ahi[r * PAD + d] = hi;
        Alo[r * PAD + d] = __float2half_rn(v - __half2float(hi));
    }
    for (int i = tid; i < 1024; i += TPB) c2s[i] = g_c2[i];

    // ldmatrix lane address components (bytes)
    const uint32_t aRow = (uint32_t)((lane & 15) * PAD + (lane >> 4) * 8) * 2;
    const uint32_t aHiBase = sb + OFF_AHI + (uint32_t)(mblk * PAD * 2) + aRow;
    const uint32_t aLoBase = sb + OFF_ALO + (uint32_t)(mblk * PAD * 2) + aRow;
    const uint32_t bLane = (uint32_t)(((lane & 7) + ((lane >> 4) << 3)) * PAD + (((lane >> 3) & 1) << 3)) * 2;
    const uint32_t bHiBase = sb + OFF_B + (uint32_t)(nblk * PAD * 2) + bLane;
    const uint32_t bLoBase = bHiBase + BTERM_BYTES;

    float acc[2][8][4];
#pragma unroll
    for (int mi = 0; mi < 2; mi++)
#pragma unroll
        for (int nt = 0; nt < 8; nt++)
#pragma unroll
            for (int j = 0; j < 4; j++) acc[mi][nt][j] = 0.f;

    float runM[4]; int runI[4];
#pragma unroll
    for (int i = 0; i < 4; i++) { runM[i] = 3.4e38f; runI[i] = 0; }

    for (int c = 0; c < NCHUNKS; c++) {
        __syncthreads();   // previous chunk's compute done before overwrite
        // load chunk c (hi+lo) as 2304 x 16B vector copies
        for (int j = tid; j < 2304; j += TPB) {
            int term = (j >= 1152);
            int jj = term ? j - 1152 : j;
            int r = jj / 9, s = jj % 9;
            const float4* src = (const float4*)((term ? g_cbl : g_cbh) + c * CHUNK * PAD + r * PAD + s * 8);
            Bv[term * 1152 + jj] = *src;
        }
        __syncthreads();

#pragma unroll
        for (int ks = 0; ks < 4; ks++) {
            uint32_t ah[2][4], al[2][4];
#pragma unroll
            for (int mi = 0; mi < 2; mi++) {
                uint32_t ao = (uint32_t)(mi * 16 * PAD + ks * 16) * 2;
                LDSM_X4(ah[mi][0], ah[mi][1], ah[mi][2], ah[mi][3], aHiBase + ao);
                LDSM_X4(al[mi][0], al[mi][1], al[mi][2], al[mi][3], aLoBase + ao);
            }
#pragma unroll
            for (int p = 0; p < 4; p++) {
                uint32_t bo = (uint32_t)(p * 16 * PAD + ks * 16) * 2;
                uint32_t bh0, bh1, bh2, bh3, bl0, bl1, bl2, bl3;
                LDSM_X4(bh0, bh1, bh2, bh3, bHiBase + bo);
                LDSM_X4(bl0, bl1, bl2, bl3, bLoBase + bo);
#pragma unroll
                for (int mi = 0; mi < 2; mi++) {
                    MMA16816(acc[mi][2 * p + 0], ah[mi], bh0, bh1);   // hi*hi
                    MMA16816(acc[mi][2 * p + 0], ah[mi], bl0, bl1);   // hi*lo
                    MMA16816(acc[mi][2 * p + 0], al[mi], bh0, bh1);   // lo*hi
                    MMA16816(acc[mi][2 * p + 1], ah[mi], bh2, bh3);
                    MMA16816(acc[mi][2 * p + 1], ah[mi], bl2, bl3);
                    MMA16816(acc[mi][2 * p + 1], al[mi], bh2, bh3);
                }
            }
        }

        // fold distances: dist = |c|^2 - 2 x.c ; ascending code order per thread
        const int cbase = c * CHUNK + nblk + 2 * (lane & 3);
#pragma unroll
        for (int nt = 0; nt < 8; nt++) {
            int col = cbase + nt * 8;
            float c20 = c2s[col], c21 = c2s[col + 1];
#pragma unroll
            for (int mi = 0; mi < 2; mi++)
#pragma unroll
                for (int h = 0; h < 2; h++) {
                    int ridx = mi * 2 + h;
                    float d0 = fmaf(-2.f, acc[mi][nt][h * 2 + 0], c20);
                    float d1 = fmaf(-2.f, acc[mi][nt][h * 2 + 1], c21);
                    if (d0 < runM[ridx]) { runM[ridx] = d0; runI[ridx] = col; }
                    if (d1 < runM[ridx]) { runM[ridx] = d1; runI[ridx] = col + 1; }
                    acc[mi][nt][h * 2 + 0] = 0.f;
                    acc[mi][nt][h * 2 + 1] = 0.f;
                }
        }
    }

    // quad reduce (lanes sharing a row), lexicographic (val, idx)
#pragma unroll
    for (int off = 1; off <= 2; off <<= 1) {
#pragma unroll
        for (int ridx = 0; ridx < 4; ridx++) {
            float om = __shfl_xor_sync(0xffffffffu, runM[ridx], off);
            int   oi = __shfl_xor_sync(0xffffffffu, runI[ridx], off);
            if (om < runM[ridx] || (om == runM[ridx] && oi < runI[ridx])) {
                runM[ridx] = om; runI[ridx] = oi;
            }
        }
    }
    if ((lane & 3) == 0) {
#pragma unroll
        for (int ridx = 0; ridx < 4; ridx++) {
            int mi = ridx >> 1, h = ridx & 1;
            int row = mblk + mi * 16 + (lane >> 2) + h * 8;
            redV[row * 2 + nb] = runM[ridx];
            redI[row * 2 + nb] = runI[ridx];
        }
    }
    __syncthreads();

    if (tid < BM) {
        float v0 = redV[tid * 2], v1 = redV[tid * 2 + 1];
        int i0 = redI[tid * 2], i1 = redI[tid * 2 + 1];
        int bi = (v1 < v0 || (v1 == v0 && i1 < i0)) ? i1 : i0;
        bestI[tid] = bi;
        int gr = rowBase + tid;
        if (gr < N) {
            if (writeExtras) outT[gr] = (float)bi;
            atomicAdd(&g_counts[bi], 1);
        }
    }
    __syncthreads();

    // quantized write + MSE
    float lsum = 0.f;
    for (int r = warp; r < BM; r += 8) {
        int gr = rowBase + r;
        if (gr >= N) continue;
        int bi = bestI[r];
        const float* crow = cb + (size_t)bi * D;
        float* qrow = outQ + (size_t)gr * D;
#pragma unroll
        for (int h = 0; h < 2; h++) {
            int d = h * 32 + lane;
            float cv = __ldg(&crow[d]);
            float xv = __half2float(Ahi[r * PAD + d]) + __half2float(Alo[r * PAD + d]);
            float diff = xv - cv;
            lsum = fmaf(diff, diff, lsum);
            qrow[d] = cv;
        }
    }
#pragma unroll
    for (int o = 16; o > 0; o >>= 1) lsum += __shfl_down_sync(0xffffffffu, lsum, o);
    if (lane == 0) wsum[warp] = lsum;
    __syncthreads();
    if (tid == 0) {
        float s = 0.f;
#pragma unroll
        for (int w = 0; w < 8; w++) s += wsum[w];
        atomicAdd(&g_mse_sum, (double)s);
    }
}

// ---------------- scalars ----------------
__global__ void vq_final(float* __restrict__ outS, int N) {
    const int tid = threadIdx.x;
    float ent = 0.f;
    for (int k = tid; k < 1024; k += blockDim.x) {
        float p = (float)g_counts[k] / (float)N;
        ent += p * logf(p + 1e-10f);
    }
#pragma unroll
    for (int o = 16; o > 0; o >>= 1) ent += __shfl_down_sync(0xffffffffu, ent, o);
    __shared__ float ws[32];
    const int warp = tid >> 5, lane = tid & 31;
    if (lane == 0) ws[warp] = ent;
    __syncthreads();
    if (tid == 0) {
        float e = 0.f;
        int nw = (blockDim.x + 31) >> 5;
        for (int w = 0; w < nw; w++) e += ws[w];
        float mse = (float)(g_mse_sum / ((double)N * (double)D));
        outS[0] = 1.25f * mse;
        outS[1] = 0.25f * mse;
        outS[2] = mse;
        outS[3] = expf(-e);
    }
}

extern "C" void kernel_launch(void* const* d_in, const int* in_sizes, int n_in,
                              void* d_out, int out_size)
{
    const float* x  = (const float*)d_in[0];
    const float* cb = (const float*)d_in[1];
    const int total = in_sizes[0];
    const int N = total / D;

    float* out = (float*)d_out;
    const int writeExtras = (out_size >= total + N + 4) ? 1 : 0;
    float* outQ = out;
    float* outT = writeExtras ? out + total : out;
    float* outS = writeExtras ? out + total + N : nullptr;

    cudaFuncSetAttribute(vq_main, cudaFuncAttributeMaxDynamicSharedMemorySize, SMEM_TOTAL);

    vq_prep<<<KCODES, D>>>(cb);
    const int grid = (N + BM - 1) / BM;
    vq_main<<<grid, TPB, SMEM_TOTAL>>>(x, cb, N, outQ, outT, writeExtras);
    if (writeExtras)
        vq_final<<<1, 1024>>>(outS, N);
}